// round 1
// baseline (speedup 1.0000x reference)
#include <cuda_runtime.h>
#include <math.h>

// ---------------- problem constants ----------------
#define D_MODEL 768
#define N_HEADS 12
#define D_HEAD  64
#define N_MEM   3072
#define BB      8
#define SS      1024
#define ROWS    (BB*SS)        // 8192
#define ZB      (BB*N_HEADS)   // 96 batched (b,h) slices
#define ALPHA_F 0.1f
#define EPS_F   1e-5f
#define NSTEPS  12

// ---------------- scratch layout (floats) ----------------
constexpr long L_G   = (long)ROWS * D_MODEL;     // 6,291,456
constexpr long L_QK  = (long)ROWS * 1536;        // 12,582,912
constexpr long L_H   = (long)ROWS * N_MEM;       // 25,165,824
constexpr long L_W   = 1536L * 768;              // 1,179,648
constexpr long L_A   = (long)ZB * SS * SS;       // 100,663,296

constexpr long OFF_G     = 0;
constexpr long OFF_QK    = OFF_G     + L_G;
constexpr long OFF_AQAK  = OFF_QK    + L_QK;
constexpr long OFF_GATTN = OFF_AQAK  + L_QK;
constexpr long OFF_GHOP  = OFF_GATTN + L_G;
constexpr long OFF_H     = OFF_GHOP  + L_G;
constexpr long OFF_WQK   = OFF_H     + L_H;
constexpr long OFF_RSTD  = OFF_WQK   + L_W;
constexpr long OFF_MEAN  = OFF_RSTD  + ROWS;
constexpr long OFF_LSE   = OFF_MEAN  + ROWS;
constexpr long OFF_A     = OFF_LSE   + (long)ZB * SS;
constexpr long TOTAL_F   = OFF_A     + L_A;      // ~171.2M floats (~685 MB)

__device__ float g_buf[TOTAL_F];

// ---------------- reductions ----------------
__device__ __forceinline__ float warpReduceSum(float v) {
    #pragma unroll
    for (int o = 16; o > 0; o >>= 1) v += __shfl_xor_sync(0xffffffffu, v, o);
    return v;
}
__device__ __forceinline__ float warpReduceMax(float v) {
    #pragma unroll
    for (int o = 16; o > 0; o >>= 1) v = fmaxf(v, __shfl_xor_sync(0xffffffffu, v, o));
    return v;
}
__device__ __forceinline__ float blockReduceSum(float v) {
    __shared__ float sh[32];
    int lane = threadIdx.x & 31, wid = threadIdx.x >> 5;
    __syncthreads();                 // guard WAR on sh reuse across calls
    v = warpReduceSum(v);
    if (lane == 0) sh[wid] = v;
    __syncthreads();
    int nw = (blockDim.x + 31) >> 5;
    v = (threadIdx.x < nw) ? sh[threadIdx.x] : 0.f;
    if (wid == 0) v = warpReduceSum(v);
    return v;                        // valid in warp 0
}
__device__ __forceinline__ float blockReduceMax(float v) {
    __shared__ float sh[32];
    int lane = threadIdx.x & 31, wid = threadIdx.x >> 5;
    __syncthreads();
    v = warpReduceMax(v);
    if (lane == 0) sh[wid] = v;
    __syncthreads();
    int nw = (blockDim.x + 31) >> 5;
    v = (threadIdx.x < nw) ? sh[threadIdx.x] : -3.4e38f;
    if (wid == 0) v = warpReduceMax(v);
    return v;
}

// ---------------- LN forward ----------------
// g = gamma*(x-mean)*rstd + delta ; store mean, rstd per row.
__global__ void ln_forward_kernel(const float* __restrict__ x,
                                  const float* __restrict__ gamma,
                                  const float* __restrict__ delta,
                                  float* __restrict__ g,
                                  float* __restrict__ rstd_o,
                                  float* __restrict__ mean_o) {
    int row = blockIdx.x;
    const float* xr = x + (long)row * D_MODEL;
    int t = threadIdx.x;                      // 256 threads, 3 elems each
    float v[3]; float s = 0.f;
    #pragma unroll
    for (int i = 0; i < 3; i++) { v[i] = xr[t + i*256]; s += v[i]; }
    s = blockReduceSum(s);
    __shared__ float sh_mean, sh_rstd;
    if (threadIdx.x == 0) sh_mean = s * (1.0f / D_MODEL);
    __syncthreads();
    float mean = sh_mean;
    float q = 0.f;
    #pragma unroll
    for (int i = 0; i < 3; i++) { float d = v[i] - mean; q += d*d; }
    q = blockReduceSum(q);
    if (threadIdx.x == 0) sh_rstd = rsqrtf(q * (1.0f / D_MODEL) + EPS_F);
    __syncthreads();
    float rstd = sh_rstd;
    float gm = gamma[0];
    float* gr = g + (long)row * D_MODEL;
    #pragma unroll
    for (int i = 0; i < 3; i++)
        gr[t + i*256] = gm * (v[i] - mean) * rstd + delta[t + i*256];
    if (threadIdx.x == 0) { rstd_o[row] = rstd; mean_o[row] = mean; }
}

// ---------------- row LSE over scores ----------------
__global__ void lse_kernel(const float* __restrict__ A, float* __restrict__ lse) {
    long row = blockIdx.x;                    // ZB*SS rows of length SS
    const float* ar = A + row * SS;
    int t = threadIdx.x;                      // 256 threads, 4 each
    float v[4]; float m = -3.4e38f;
    #pragma unroll
    for (int i = 0; i < 4; i++) { v[i] = ar[t + i*256]; m = fmaxf(m, v[i]); }
    m = blockReduceMax(m);
    __shared__ float sh_m;
    if (threadIdx.x == 0) sh_m = m;
    __syncthreads();
    m = sh_m;
    float s = 0.f;
    #pragma unroll
    for (int i = 0; i < 4; i++) s += __expf(v[i] - m);
    s = blockReduceSum(s);
    if (threadIdx.x == 0) lse[row] = m + __logf(s);
}

// ---------------- fused LN-backward + update ----------------
// u = x - gattn_pos - ghop_pos ; grad = gamma*rstd*(u - mean(u) - ghat*mean(u*ghat))
__global__ void update_kernel(float* __restrict__ x,
                              const float* __restrict__ ga,
                              const float* __restrict__ gh,
                              const float* __restrict__ gamma,
                              const float* __restrict__ mean_a,
                              const float* __restrict__ rstd_a) {
    int row = blockIdx.x;
    long base = (long)row * D_MODEL;
    int t = threadIdx.x;
    float mean = mean_a[row], rstd = rstd_a[row];
    float xv[3], uv[3], gv[3];
    float s1 = 0.f, s2 = 0.f;
    #pragma unroll
    for (int i = 0; i < 3; i++) {
        long idx = base + t + i*256;
        xv[i] = x[idx];
        uv[i] = xv[i] - ga[idx] - gh[idx];
        gv[i] = (xv[i] - mean) * rstd;
        s1 += uv[i]; s2 += uv[i] * gv[i];
    }
    s1 = blockReduceSum(s1);
    __shared__ float sh1, sh2;
    if (threadIdx.x == 0) sh1 = s1;
    s2 = blockReduceSum(s2);
    if (threadIdx.x == 0) sh2 = s2;
    __syncthreads();
    float mu = sh1 * (1.0f / D_MODEL);
    float mg = sh2 * (1.0f / D_MODEL);
    float gm = gamma[0];
    #pragma unroll
    for (int i = 0; i < 3; i++) {
        float grad = gm * rstd * (uv[i] - mu - gv[i] * mg);
        x[base + t + i*256] = xv[i] - ALPHA_F * grad;
    }
}

// ---------------- generic tiled fp32 GEMM ----------------
// C[m,n] = alpha * sum_k opA(A)[m,k] * opB(B)[k,n]
// TA=0: A[m*lda+k]      TA=1: A[k*lda+m]   (transposed-A storage)
// TB=1: B[n*ldb+k] (NT)  TB=0: B[k*ldb+n]  (NN)
// PRO: 0 none | 1 relu(a) | 2 a=exp(a-lse[m]) | 3 a=exp(a-lse[k])
// Batched over blockIdx.z: z = b*N_HEADS + h; per-operand (b,h) strides.
template<int BM, int BN, int BK, int TM, int TN, int TA, int TB, int PRO>
__global__ void __launch_bounds__((BM/TM)*(BN/TN))
gemm_kernel(const float* __restrict__ A, int lda, long sAb, long sAh,
            const float* __restrict__ B, int ldb, long sBb, long sBh,
            float* __restrict__ C, int ldc, long sCb, long sCh,
            int M, int N, int K,
            const float* __restrict__ lse,
            const float* __restrict__ alphaPtr) {
    constexpr int NT = (BM/TM) * (BN/TN);
    int z  = blockIdx.z;
    int zb = z / N_HEADS, zh = z % N_HEADS;
    A += zb * sAb + zh * sAh;
    B += zb * sBb + zh * sBh;
    C += zb * sCb + zh * sCh;
    const float* lsez = lse ? (lse + (long)z * SS) : nullptr;

    __shared__ float As[BK][BM];
    __shared__ float Bs[BK][BN];
    int bm  = blockIdx.y * BM;
    int bn  = blockIdx.x * BN;
    int tid = threadIdx.x;
    int tx  = tid % (BN / TN);
    int ty  = tid / (BN / TN);

    float acc[TM][TN];
    #pragma unroll
    for (int i = 0; i < TM; i++)
        #pragma unroll
        for (int j = 0; j < TN; j++) acc[i][j] = 0.f;

    for (int k0 = 0; k0 < K; k0 += BK) {
        // --- A tile ---
        #pragma unroll
        for (int r = 0; r < (BM*BK)/NT; r++) {
            int i = tid + r * NT;
            int m, kk; float v;
            if (TA == 0) { m = i / BK; kk = i % BK; v = A[(long)(bm + m) * lda + (k0 + kk)]; }
            else         { kk = i / BM; m = i % BM; v = A[(long)(k0 + kk) * lda + (bm + m)]; }
            if      (PRO == 1) v = fmaxf(v, 0.f);
            else if (PRO == 2) v = __expf(v - lsez[bm + m]);
            else if (PRO == 3) v = __expf(v - lsez[k0 + kk]);
            As[kk][m] = v;
        }
        // --- B tile ---
        #pragma unroll
        for (int r = 0; r < (BN*BK)/NT; r++) {
            int i = tid + r * NT;
            int n, kk; float v;
            if (TB == 1) { n = i / BK; kk = i % BK; v = B[(long)(bn + n) * ldb + (k0 + kk)]; }
            else         { kk = i / BN; n = i % BN; v = B[(long)(k0 + kk) * ldb + (bn + n)]; }
            Bs[kk][n] = v;
        }
        __syncthreads();
        #pragma unroll
        for (int kk = 0; kk < BK; kk++) {
            float af[TM], bf[TN];
            #pragma unroll
            for (int i = 0; i < TM; i++) af[i] = As[kk][ty * TM + i];
            #pragma unroll
            for (int j = 0; j < TN; j++) bf[j] = Bs[kk][tx * TN + j];
            #pragma unroll
            for (int i = 0; i < TM; i++)
                #pragma unroll
                for (int j = 0; j < TN; j++) acc[i][j] += af[i] * bf[j];
        }
        __syncthreads();
    }
    float alpha = alphaPtr ? alphaPtr[zh] : 1.0f;
    #pragma unroll
    for (int i = 0; i < TM; i++)
        #pragma unroll
        for (int j = 0; j < TN; j++)
            C[(long)(bm + ty * TM + i) * ldc + (bn + tx * TN + j)] = alpha * acc[i][j];
}

// ---------------- driver ----------------
extern "C" void kernel_launch(void* const* d_in, const int* in_sizes, int n_in,
                              void* d_out, int out_size) {
    const float* x_in  = (const float*)d_in[0];
    const float* gamma = (const float*)d_in[1];
    const float* delta = (const float*)d_in[2];
    const float* Wq    = (const float*)d_in[3];
    const float* Wk    = (const float*)d_in[4];
    const float* beta  = (const float*)d_in[5];
    const float* xi    = (const float*)d_in[6];
    float* x = (float*)d_out;

    float* buf = nullptr;
    cudaGetSymbolAddress((void**)&buf, g_buf);
    float* G     = buf + OFF_G;
    float* QK    = buf + OFF_QK;
    float* AqAk  = buf + OFF_AQAK;
    float* Gattn = buf + OFF_GATTN;
    float* Ghop  = buf + OFF_GHOP;
    float* Hbuf  = buf + OFF_H;
    float* Wqk   = buf + OFF_WQK;
    float* rstd  = buf + OFF_RSTD;
    float* meanb = buf + OFF_MEAN;
    float* lseb  = buf + OFF_LSE;
    float* Abuf  = buf + OFF_A;

    // x <- input ; Wqk = [Wq ; Wk] concatenated once (weights are constant)
    cudaMemcpyAsync(x, x_in, sizeof(float) * L_G, cudaMemcpyDeviceToDevice);
    cudaMemcpyAsync(Wqk, Wq, sizeof(float) * 768 * 768, cudaMemcpyDeviceToDevice);
    cudaMemcpyAsync(Wqk + 768 * 768, Wk, sizeof(float) * 768 * 768, cudaMemcpyDeviceToDevice);

    const long sA_hd = 1024L * 1536;   // per-batch row-block stride in QK/AqAk
    const long sA_zz = (long)SS * SS;  // per-(b,h) score slice

    for (int step = 0; step < NSTEPS; step++) {
        // 1. LN forward
        ln_forward_kernel<<<ROWS, 256>>>(x, gamma, delta, G, rstd, meanb);

        // 2. QK = g @ Wqk^T  (8192 x 1536, K=768); layout (b,s, h*64+y | 768+h*64+y)
        gemm_kernel<128,128,16,8,8,0,1,0><<<dim3(1536/128, ROWS/128, 1), 256>>>(
            G, D_MODEL, 0, 0, Wqk, D_MODEL, 0, 0,
            QK, 1536, 0, 0, ROWS, 1536, D_MODEL, nullptr, nullptr);

        // 3. scores A = beta_h * Q_bh K_bh^T  (batched 96 x [1024x1024], K=64)
        gemm_kernel<128,128,16,8,8,0,1,0><<<dim3(SS/128, SS/128, ZB), 256>>>(
            QK,        1536, sA_hd, 64,
            QK + 768,  1536, sA_hd, 64,
            Abuf, SS, (long)N_HEADS * sA_zz, sA_zz,
            SS, SS, D_HEAD, nullptr, beta);

        // 4. row lse
        lse_kernel<<<ZB * SS, 256>>>(Abuf, lseb);

        // 5. Aq = P K  -> AqAk[:, h*64+y]   (exp(A - lse[row]) prologue)
        gemm_kernel<128,64,16,8,4,0,0,2><<<dim3(1, SS/128, ZB), 256>>>(
            Abuf, SS, (long)N_HEADS * sA_zz, sA_zz,
            QK + 768, 1536, sA_hd, 64,
            AqAk, 1536, sA_hd, 64,
            SS, D_HEAD, SS, lseb, nullptr);

        // 6. Ak = P^T Q -> AqAk[:, 768+h*64+y] (transposed-A, exp(A - lse[q]))
        gemm_kernel<128,64,16,8,4,1,0,3><<<dim3(1, SS/128, ZB), 256>>>(
            Abuf, SS, (long)N_HEADS * sA_zz, sA_zz,
            QK, 1536, sA_hd, 64,
            AqAk + 768, 1536, sA_hd, 64,
            SS, D_HEAD, SS, lseb, nullptr);

        // 7. Gattn_pos = AqAk @ Wqk  (8192 x 768, K=1536)
        gemm_kernel<128,128,16,8,8,0,0,0><<<dim3(D_MODEL/128, ROWS/128, 1), 256>>>(
            AqAk, 1536, 0, 0, Wqk, D_MODEL, 0, 0,
            Gattn, D_MODEL, 0, 0, ROWS, D_MODEL, 1536, nullptr, nullptr);

        // 8. H = g @ xi^T  (8192 x 3072, K=768)
        gemm_kernel<128,128,16,8,8,0,1,0><<<dim3(N_MEM/128, ROWS/128, 1), 256>>>(
            G, D_MODEL, 0, 0, xi, D_MODEL, 0, 0,
            Hbuf, N_MEM, 0, 0, ROWS, N_MEM, D_MODEL, nullptr, nullptr);

        // 9. Ghop_pos = relu(H) @ xi  (8192 x 768, K=3072)
        gemm_kernel<128,128,16,8,8,0,0,1><<<dim3(D_MODEL/128, ROWS/128, 1), 256>>>(
            Hbuf, N_MEM, 0, 0, xi, D_MODEL, 0, 0,
            Ghop, D_MODEL, 0, 0, ROWS, D_MODEL, N_MEM, nullptr, nullptr);

        // 10. u = x - Gattn - Ghop ; x -= ALPHA * J_LN^T u
        update_kernel<<<ROWS, 256>>>(x, Gattn, Ghop, gamma, meanb, rstd);
    }
}